// round 15
// baseline (speedup 1.0000x reference)
#include <cuda_runtime.h>
#include <cuda_fp16.h>
#include <math.h>
#include <stdint.h>

#define N_NODES 100000
#define N_EDGES 200000
#define NNZ_    1600000
#define INC 128
#define OUTC 128
#define STAR_ 64
#define KTOT 192

#define GX_BLOCKS 1563
#define SC_BLOCKS 6250

typedef unsigned long long u64;

// ---------------- device scratch (allocation-free) ----------------
// packed per-node row: [P = w*X_feat fp16 (64 uint32) | w fp32-bits (1) | pad (3)]  stride 68
__device__ uint32_t g_XW16[(size_t)N_NODES * 68];      // 27.2 MB
// combined fp16 message row per edge: [Yv2e (128 halves) | S (64 halves)] = 96 uint32
__device__ uint32_t g_M16[(size_t)N_EDGES * 96];       // 76.8 MB

// zero region: [histE | histV | alloc_ctr(2)]  -> single memset
__device__ int g_zero[N_EDGES + N_NODES + 2];
__device__ int g_baseE[N_EDGES];
__device__ int g_baseV[N_NODES];
__device__ int g_rankE[NNZ_];
__device__ int g_rankV[NNZ_];
__device__ int g_csrE_v[NNZ_];
__device__ int g_csrV_e[NNZ_];

// ---------------- helpers ----------------
__device__ __forceinline__ float elu1(float x) {
    return x > 0.f ? x : expm1f(x);
}
// packed f32x2 FMA (Blackwell FFMA2 path via PTX)
__device__ __forceinline__ u64 pack2(float v) {
    u64 r; asm("mov.b64 %0, {%1, %1};" : "=l"(r) : "f"(v)); return r;
}
__device__ __forceinline__ void fma2(u64& d, u64 a, u64 b) {
    asm("fma.rn.f32x2 %0, %1, %2, %0;" : "+l"(d) : "l"(a), "l"(b));
}
__device__ __forceinline__ float2 unpack2(u64 v) {
    float2 r; asm("mov.b64 {%0, %1}, %2;" : "=f"(r.x), "=f"(r.y) : "l"(v)); return r;
}
__device__ __forceinline__ float2 h2f(uint32_t u) {
    return __half22float2(*reinterpret_cast<__half2*>(&u));
}
__device__ __forceinline__ uint32_t f2h(float a, float b) {
    __half2 h = __floats2half2_rn(a, b);
    return *reinterpret_cast<uint32_t*>(&h);
}
__device__ __forceinline__ uint32_t hadd2u(uint32_t a, uint32_t b) {
    __half2 r = __hadd2(*reinterpret_cast<const __half2*>(&a), *reinterpret_cast<const __half2*>(&b));
    return *reinterpret_cast<uint32_t*>(&r);
}

// ---------------- histogram + rank capture ----------------
__global__ __launch_bounds__(256) void hist_kernel(const int* __restrict__ V, const int* __restrict__ E)
{
    int i = blockIdx.x * 256 + threadIdx.x;     // 6250*256 = NNZ exact
    int e = __ldg(&E[i]);
    int v = __ldg(&V[i]);
    g_rankE[i] = atomicAdd(&g_zero[e], 1);
    g_rankV[i] = atomicAdd(&g_zero[N_EDGES + v], 1);
}

// ---------------- segment-base allocation: edges (blocks 0..781) + nodes (blocks 782..1172) ----------------
__global__ __launch_bounds__(256) void alloc_kernel()
{
    __shared__ int s_warp[8];
    __shared__ int s_base;
    const int t = threadIdx.x;
    const bool isE = blockIdx.x < 782;
    const int i = (isE ? blockIdx.x : (blockIdx.x - 782)) * 256 + t;
    const int len = isE ? N_EDGES : N_NODES;
    const int* hist = isE ? g_zero : (g_zero + N_EDGES);
    int* base = isE ? g_baseE : g_baseV;
    int* ctr  = &g_zero[N_EDGES + N_NODES + (isE ? 0 : 1)];

    const int lane = t & 31, wid = t >> 5;
    int v = (i < len) ? hist[i] : 0;
    int x = v;
    #pragma unroll
    for (int off = 1; off < 32; off <<= 1) {
        int y = __shfl_up_sync(0xffffffffu, x, off);
        if (lane >= off) x += y;
    }
    if (lane == 31) s_warp[wid] = x;
    __syncthreads();
    if (wid == 0) {
        int orig = (lane < 8) ? s_warp[lane] : 0;
        int s = orig;
        #pragma unroll
        for (int off = 1; off < 8; off <<= 1) {
            int y = __shfl_up_sync(0xffffffffu, s, off);
            if (lane >= off) s += y;
        }
        if (lane == 7) s_base = atomicAdd(ctr, s);
        if (lane < 8) s_warp[lane] = s - orig;
    }
    __syncthreads();
    if (i < len) base[i] = (x - v) + s_warp[wid] + s_base;
}

// ---------------- fused: gemm_x (blocks 0..1562) || atomic-free scatter (blocks 1563..7812) ----------------
__global__ __launch_bounds__(256, 2) void gemm_scatter_kernel(
    const float* __restrict__ X, const float* __restrict__ Wx, const float* __restrict__ bx,
    const float* __restrict__ Wv, const float* __restrict__ bv, const float* __restrict__ a_vec,
    const int* __restrict__ V, const int* __restrict__ E,
    float* __restrict__ Xinit)
{
    const int tx = threadIdx.x;

    if (blockIdx.x >= GX_BLOCKS) {
        // ----- scatter branch: pure writes, no atomics -----
        int i = (blockIdx.x - GX_BLOCKS) * 256 + tx;     // NNZ exact
        int v = __ldg(&V[i]);
        int e = __ldg(&E[i]);
        g_csrE_v[__ldg(&g_baseE[e]) + g_rankE[i]] = v;
        g_csrV_e[__ldg(&g_baseV[v]) + g_rankV[i]] = e;
        return;
    }

    // ----- gemm_x branch -----
    extern __shared__ float sm[];
    float* sXT = sm;                 // 128*72  (k-major, transposed X tile)
    float* sWx = sm + 128 * 72;      // 64*132  (one k-chunk)
    float* sWv = sWx + 64 * 132;     // 64*132

    const int n0 = blockIdx.x * 64;

    #pragma unroll
    for (int it = 0; it < 8; it++) {
        int idx = tx + it * 256;
        int row = idx >> 5;
        int kq  = idx & 31;
        int n = n0 + row;
        float4 v = make_float4(0.f, 0.f, 0.f, 0.f);
        if (n < N_NODES) v = *(const float4*)&X[(size_t)n * INC + kq * 4];
        sXT[(kq * 4 + 0) * 72 + row] = v.x;
        sXT[(kq * 4 + 1) * 72 + row] = v.y;
        sXT[(kq * 4 + 2) * 72 + row] = v.z;
        sXT[(kq * 4 + 3) * 72 + row] = v.w;
    }

    const int c0 = (tx & 31) * 4;
    const int r0 = (tx >> 5) * 8;

    u64 ax0[8], ax1[8], av0[8], av1[8];
    #pragma unroll
    for (int i = 0; i < 8; i++) { ax0[i] = 0ull; ax1[i] = 0ull; av0[i] = 0ull; av1[i] = 0ull; }

    #pragma unroll
    for (int c = 0; c < 2; c++) {
        #pragma unroll
        for (int it = 0; it < 8; it++) {
            int idx = tx + it * 256;          // 64 rows * 32 float4
            int k  = idx >> 5;
            int cq = idx & 31;
            *(float4*)&sWx[k * 132 + cq * 4] = *(const float4*)&Wx[(c * 64 + k) * OUTC + cq * 4];
            *(float4*)&sWv[k * 132 + cq * 4] = *(const float4*)&Wv[(c * 64 + k) * OUTC + cq * 4];
        }
        __syncthreads();

        #pragma unroll 4
        for (int kk = 0; kk < 64; kk++) {
            int k = c * 64 + kk;
            ulonglong2 wx = *(ulonglong2*)&sWx[kk * 132 + c0];
            ulonglong2 wv = *(ulonglong2*)&sWv[kk * 132 + c0];
            float4 xa = *(float4*)&sXT[k * 72 + r0];
            float4 xb = *(float4*)&sXT[k * 72 + r0 + 4];
            float xs[8] = {xa.x, xa.y, xa.z, xa.w, xb.x, xb.y, xb.z, xb.w};
            #pragma unroll
            for (int i = 0; i < 8; i++) {
                u64 xx = pack2(xs[i]);
                fma2(ax0[i], xx, wx.x); fma2(ax1[i], xx, wx.y);
                fma2(av0[i], xx, wv.x); fma2(av1[i], xx, wv.y);
            }
        }
        __syncthreads();
    }

    float4 bx4 = *(const float4*)&bx[c0];
    float4 bv4 = *(const float4*)&bv[c0];
    float4 aa4 = *(const float4*)&a_vec[c0];
    const int lane = tx & 31;
    #pragma unroll
    for (int i = 0; i < 8; i++) {
        int n = n0 + r0 + i;
        if (n < N_NODES) {   // warp-uniform guard
            float2 x01 = unpack2(ax0[i]), x23 = unpack2(ax1[i]);
            float4 o = make_float4(x01.x + bx4.x, x01.y + bx4.y, x23.x + bx4.z, x23.y + bx4.w);
            *(float4*)&Xinit[(size_t)n * OUTC + c0] = o;
            float2 v01 = unpack2(av0[i]), v23 = unpack2(av1[i]);
            float4 f = make_float4(v01.x + bv4.x, v01.y + bv4.y, v23.x + bv4.z, v23.y + bv4.w);
            float part = f.x * aa4.x + f.y * aa4.y + f.z * aa4.z + f.w * aa4.w;
            #pragma unroll
            for (int off = 16; off; off >>= 1) part += __shfl_xor_sync(0xffffffffu, part, off);
            float s = part > 0.f ? part : 0.2f * part;
            float wv = expf(s);                         // warp-instruction cost, all lanes free
            uint2 pk; pk.x = f2h(wv * f.x, wv * f.y); pk.y = f2h(wv * f.z, wv * f.w);
            *(uint2*)&g_XW16[(size_t)n * 68 + lane * 2] = pk;     // P = w * X_feat
            if (lane == 0) g_XW16[(size_t)n * 68 + 64] = __float_as_uint(wv);
        }
    }
}

// ---------------- edge aggregation: M16[e] = [ fp16(elu(sum P[v]/sum w_v)) | fp16(S[e]) ] ----------------
// pure pairwise-HADD2 gather — no multiplies in the loop
__global__ __launch_bounds__(256) void edge_agg_kernel(const float* __restrict__ S)
{
    const int e = blockIdx.x * 8 + (threadIdx.x >> 5);   // 25000*8 = 200000
    const int lane = threadIdx.x & 31;
    const int base = g_baseE[e];
    const int deg  = g_zero[e];
    float2 accA = make_float2(0.f, 0.f);
    float2 accB = make_float2(0.f, 0.f);
    float denom = 0.f;
    int j = 0;
    for (; j + 1 < deg; j += 2) {
        int v0 = __ldg(&g_csrE_v[base + j]);
        int v1 = __ldg(&g_csrE_v[base + j + 1]);
        const uint32_t* r0 = &g_XW16[(size_t)v0 * 68];
        const uint32_t* r1 = &g_XW16[(size_t)v1 * 68];
        uint2 p0 = *(const uint2*)&r0[lane * 2];
        uint2 p1 = *(const uint2*)&r1[lane * 2];
        denom += __uint_as_float(__ldg(&r0[64])) + __uint_as_float(__ldg(&r1[64]));
        float2 sA = h2f(hadd2u(p0.x, p1.x));
        float2 sB = h2f(hadd2u(p0.y, p1.y));
        accA.x += sA.x; accA.y += sA.y;
        accB.x += sB.x; accB.y += sB.y;
    }
    if (j < deg) {   // odd tail in fp32
        int v0 = __ldg(&g_csrE_v[base + j]);
        const uint32_t* r0 = &g_XW16[(size_t)v0 * 68];
        uint2 p0 = *(const uint2*)&r0[lane * 2];
        denom += __uint_as_float(__ldg(&r0[64]));
        float2 f0 = h2f(p0.x), f1 = h2f(p0.y);
        accA.x += f0.x; accA.y += f0.y;
        accB.x += f1.x; accB.y += f1.y;
    }
    float inv = (deg > 0) ? (1.f / denom) : 0.f;
    uint2 pk;
    pk.x = f2h(elu1(accA.x * inv), elu1(accA.y * inv));
    pk.y = f2h(elu1(accB.x * inv), elu1(accB.y * inv));
    *(uint2*)&g_M16[(size_t)e * 96 + lane * 2] = pk;
    // append fp16(S[e]) — read once per edge instead of once per nnz in the node pass
    float2 s2 = *(const float2*)&S[(size_t)e * STAR_ + lane * 2];
    g_M16[(size_t)e * 96 + 64 + lane] = f2h(s2.x, s2.y);
}

// ---------------- fused node aggregation + GEMM: out = X_init + (deg>0 ? elu(mean@Wt + bt) : 0) ----------------
#define SMROW 200
__global__ __launch_bounds__(256, 3) void node_gemm_fused_kernel(
    const float* __restrict__ Wt, const float* __restrict__ bt, float* __restrict__ out)
{
    extern __shared__ float sm[];
    float* sM = sm;                        // 64*200
    float* sW = sm + 64 * SMROW;           // 32*132
    int*  sDeg = (int*)(sW + 32 * 132);    // 64

    const int tx = threadIdx.x;
    const int wid = tx >> 5, lane = tx & 31;
    const int n0 = blockIdx.x * 64;

    // ---- phase 1: gather means, pairwise-fp16 reduction (HADD2 pairs, fp32 accumulate) ----
    #pragma unroll 1
    for (int m = 0; m < 8; m++) {
        int row = wid * 8 + m;
        int n = n0 + row;
        float2 accA = make_float2(0.f, 0.f);
        float2 accB = make_float2(0.f, 0.f);
        float2 accS = make_float2(0.f, 0.f);
        int deg = 0;
        if (n < N_NODES) {
            int base = g_baseV[n];
            deg = g_zero[N_EDGES + n];
            int j = 0;
            for (; j + 1 < deg; j += 2) {
                int e0 = __ldg(&g_csrV_e[base + j]);
                int e1 = __ldg(&g_csrV_e[base + j + 1]);
                const uint32_t* r0 = &g_M16[(size_t)e0 * 96];
                const uint32_t* r1 = &g_M16[(size_t)e1 * 96];
                uint32_t a0 = __ldg(&r0[lane]),      b0 = __ldg(&r1[lane]);
                uint32_t a1 = __ldg(&r0[32 + lane]), b1 = __ldg(&r1[32 + lane]);
                uint32_t a2 = __ldg(&r0[64 + lane]), b2 = __ldg(&r1[64 + lane]);
                float2 pA = h2f(hadd2u(a0, b0));
                float2 pB = h2f(hadd2u(a1, b1));
                float2 pS = h2f(hadd2u(a2, b2));
                accA.x += pA.x; accA.y += pA.y;
                accB.x += pB.x; accB.y += pB.y;
                accS.x += pS.x; accS.y += pS.y;
            }
            if (j < deg) {   // odd tail in fp32
                int e0 = __ldg(&g_csrV_e[base + j]);
                const uint32_t* r0 = &g_M16[(size_t)e0 * 96];
                float2 f0 = h2f(__ldg(&r0[lane]));
                float2 f1 = h2f(__ldg(&r0[32 + lane]));
                float2 f2 = h2f(__ldg(&r0[64 + lane]));
                accA.x += f0.x; accA.y += f0.y;
                accB.x += f1.x; accB.y += f1.y;
                accS.x += f2.x; accS.y += f2.y;
            }
        }
        float inv = 1.f / fmaxf((float)deg, 1.f);
        accA.x *= inv; accA.y *= inv;
        accB.x *= inv; accB.y *= inv;
        accS.x *= inv; accS.y *= inv;
        *(float2*)&sM[row * SMROW + 2 * lane] = accA;
        *(float2*)&sM[row * SMROW + 64 + 2 * lane] = accB;
        *(float2*)&sM[row * SMROW + 128 + 2 * lane] = accS;
        if (lane == 0) sDeg[row] = deg;
    }
    __syncthreads();

    // ---- phase 2: GEMM (64x128, K=192, Wt in 6 chunks of 32 rows) ----
    const int c0 = (tx & 31) * 4;
    const int r0 = (tx >> 5) * 8;

    u64 a0[8], a1[8];
    #pragma unroll
    for (int i = 0; i < 8; i++) { a0[i] = 0ull; a1[i] = 0ull; }

    #pragma unroll 1
    for (int c = 0; c < 6; c++) {
        #pragma unroll
        for (int it = 0; it < 4; it++) {
            int idx = tx + it * 256;      // 32 rows * 32 float4
            int k  = idx >> 5;
            int cq = idx & 31;
            *(float4*)&sW[k * 132 + cq * 4] = *(const float4*)&Wt[(c * 32 + k) * OUTC + cq * 4];
        }
        __syncthreads();

        #pragma unroll 4
        for (int kk = 0; kk < 32; kk++) {
            int k = c * 32 + kk;
            ulonglong2 w2 = *(ulonglong2*)&sW[kk * 132 + c0];
            #pragma unroll
            for (int i = 0; i < 8; i++) {
                u64 xx = pack2(sM[(r0 + i) * SMROW + k]);   // warp-broadcast LDS
                fma2(a0[i], xx, w2.x); fma2(a1[i], xx, w2.y);
            }
        }
        __syncthreads();
    }

    float4 bt4 = *(const float4*)&bt[c0];
    #pragma unroll
    for (int i = 0; i < 8; i++) {
        int n = n0 + r0 + i;
        if (n < N_NODES) {
            size_t oidx = (size_t)n * OUTC + c0;
            float4 o = *(const float4*)&out[oidx];           // X_init
            if (sDeg[r0 + i] > 0) {                          // isolated node -> elu(0)=0
                float2 p01 = unpack2(a0[i]), p23 = unpack2(a1[i]);
                o.x += elu1(p01.x + bt4.x);
                o.y += elu1(p01.y + bt4.y);
                o.z += elu1(p23.x + bt4.z);
                o.w += elu1(p23.y + bt4.w);
            }
            *(float4*)&out[oidx] = o;
        }
    }
}

// ---------------- launch ----------------
extern "C" void kernel_launch(void* const* d_in, const int* in_sizes, int n_in,
                              void* d_out, int out_size)
{
    const float* X  = (const float*)d_in[0];
    const int*   V  = (const int*)d_in[1];
    const int*   E  = (const int*)d_in[2];
    const float* S  = (const float*)d_in[3];
    const float* Wx = (const float*)d_in[4];
    const float* bx = (const float*)d_in[5];
    const float* Wv = (const float*)d_in[6];
    const float* bv = (const float*)d_in[7];
    const float* a  = (const float*)d_in[8];
    const float* Wt = (const float*)d_in[9];
    const float* bt = (const float*)d_in[10];
    float* out = (float*)d_out;

    void* p_zero;
    cudaGetSymbolAddress(&p_zero, g_zero);
    cudaMemsetAsync(p_zero, 0, (size_t)(N_EDGES + N_NODES + 2) * sizeof(int));

    const int smem1 = (128 * 72 + 2 * 64 * 132) * (int)sizeof(float);           // 104448
    const int smem2 = (64 * SMROW + 32 * 132) * (int)sizeof(float) + 64 * 4;    // 68352
    cudaFuncSetAttribute(gemm_scatter_kernel,    cudaFuncAttributeMaxDynamicSharedMemorySize, smem1);
    cudaFuncSetAttribute(node_gemm_fused_kernel, cudaFuncAttributeMaxDynamicSharedMemorySize, smem2);

    hist_kernel<<<6250, 256>>>(V, E);
    alloc_kernel<<<1173, 256>>>();
    gemm_scatter_kernel<<<GX_BLOCKS + SC_BLOCKS, 256, smem1>>>(X, Wx, bx, Wv, bv, a, V, E, out);
    edge_agg_kernel<<<25000, 256>>>(S);
    node_gemm_fused_kernel<<<1563, 256, smem2>>>(Wt, bt, out);
}

// round 16
// speedup vs baseline: 1.0173x; 1.0173x over previous
#include <cuda_runtime.h>
#include <cuda_fp16.h>
#include <math.h>
#include <stdint.h>

#define N_NODES 100000
#define N_EDGES 200000
#define NNZ_    1600000
#define INC 128
#define OUTC 128
#define STAR_ 64
#define KTOT 192

#define GX_BLOCKS 1563
#define SC_BLOCKS 6250

typedef unsigned long long u64;

// ---------------- device scratch (allocation-free) ----------------
// packed per-node row: [P = w*X_feat fp16 (64 uint32) | w fp32-bits (1) | pad (3)]  stride 68
__device__ uint32_t g_XW16[(size_t)N_NODES * 68];      // 27.2 MB
// combined fp16 message row per edge: [Yv2e (128 halves) | S (64 halves)] = 96 uint32
__device__ uint32_t g_M16[(size_t)N_EDGES * 96];       // 76.8 MB

// zero region: [histE | histV | alloc_ctr(2)]  -> single memset
__device__ int g_zero[N_EDGES + N_NODES + 2];
__device__ int g_baseE[N_EDGES];
__device__ int g_baseV[N_NODES];
__device__ int g_rankE[NNZ_];
__device__ int g_rankV[NNZ_];
__device__ int g_csrE_v[NNZ_];
__device__ int g_csrV_e[NNZ_];

// ---------------- helpers ----------------
__device__ __forceinline__ float elu1(float x) {
    return x > 0.f ? x : expm1f(x);
}
// packed f32x2 FMA (Blackwell FFMA2 path via PTX)
__device__ __forceinline__ u64 pack2(float v) {
    u64 r; asm("mov.b64 %0, {%1, %1};" : "=l"(r) : "f"(v)); return r;
}
__device__ __forceinline__ void fma2(u64& d, u64 a, u64 b) {
    asm("fma.rn.f32x2 %0, %1, %2, %0;" : "+l"(d) : "l"(a), "l"(b));
}
__device__ __forceinline__ float2 unpack2(u64 v) {
    float2 r; asm("mov.b64 {%0, %1}, %2;" : "=f"(r.x), "=f"(r.y) : "l"(v)); return r;
}
__device__ __forceinline__ float2 h2f(uint32_t u) {
    return __half22float2(*reinterpret_cast<__half2*>(&u));
}
__device__ __forceinline__ uint32_t f2h(float a, float b) {
    __half2 h = __floats2half2_rn(a, b);
    return *reinterpret_cast<uint32_t*>(&h);
}
__device__ __forceinline__ uint32_t hadd2u(uint32_t a, uint32_t b) {
    __half2 r = __hadd2(*reinterpret_cast<const __half2*>(&a), *reinterpret_cast<const __half2*>(&b));
    return *reinterpret_cast<uint32_t*>(&r);
}

// ---------------- histogram + rank capture ----------------
__global__ __launch_bounds__(256) void hist_kernel(const int* __restrict__ V, const int* __restrict__ E)
{
    int i = blockIdx.x * 256 + threadIdx.x;     // 6250*256 = NNZ exact
    int e = __ldg(&E[i]);
    int v = __ldg(&V[i]);
    g_rankE[i] = atomicAdd(&g_zero[e], 1);
    g_rankV[i] = atomicAdd(&g_zero[N_EDGES + v], 1);
}

// ---------------- segment-base allocation: edges (blocks 0..781) + nodes (blocks 782..1172) ----------------
__global__ __launch_bounds__(256) void alloc_kernel()
{
    __shared__ int s_warp[8];
    __shared__ int s_base;
    const int t = threadIdx.x;
    const bool isE = blockIdx.x < 782;
    const int i = (isE ? blockIdx.x : (blockIdx.x - 782)) * 256 + t;
    const int len = isE ? N_EDGES : N_NODES;
    const int* hist = isE ? g_zero : (g_zero + N_EDGES);
    int* base = isE ? g_baseE : g_baseV;
    int* ctr  = &g_zero[N_EDGES + N_NODES + (isE ? 0 : 1)];

    const int lane = t & 31, wid = t >> 5;
    int v = (i < len) ? hist[i] : 0;
    int x = v;
    #pragma unroll
    for (int off = 1; off < 32; off <<= 1) {
        int y = __shfl_up_sync(0xffffffffu, x, off);
        if (lane >= off) x += y;
    }
    if (lane == 31) s_warp[wid] = x;
    __syncthreads();
    if (wid == 0) {
        int orig = (lane < 8) ? s_warp[lane] : 0;
        int s = orig;
        #pragma unroll
        for (int off = 1; off < 8; off <<= 1) {
            int y = __shfl_up_sync(0xffffffffu, s, off);
            if (lane >= off) s += y;
        }
        if (lane == 7) s_base = atomicAdd(ctr, s);
        if (lane < 8) s_warp[lane] = s - orig;
    }
    __syncthreads();
    if (i < len) base[i] = (x - v) + s_warp[wid] + s_base;
}

// ---------------- fused: gemm_x (blocks 0..1562) || atomic-free scatter (blocks 1563..7812) ----------------
__global__ __launch_bounds__(256, 2) void gemm_scatter_kernel(
    const float* __restrict__ X, const float* __restrict__ Wx, const float* __restrict__ bx,
    const float* __restrict__ Wv, const float* __restrict__ bv, const float* __restrict__ a_vec,
    const int* __restrict__ V, const int* __restrict__ E,
    float* __restrict__ Xinit)
{
    const int tx = threadIdx.x;

    if (blockIdx.x >= GX_BLOCKS) {
        // ----- scatter branch: pure writes, no atomics -----
        int i = (blockIdx.x - GX_BLOCKS) * 256 + tx;     // NNZ exact
        int v = __ldg(&V[i]);
        int e = __ldg(&E[i]);
        g_csrE_v[__ldg(&g_baseE[e]) + g_rankE[i]] = v;
        g_csrV_e[__ldg(&g_baseV[v]) + g_rankV[i]] = e;
        return;
    }

    // ----- gemm_x branch -----
    extern __shared__ float sm[];
    float* sXT = sm;                 // 128*72  (k-major, transposed X tile)
    float* sWx = sm + 128 * 72;      // 64*132  (one k-chunk)
    float* sWv = sWx + 64 * 132;     // 64*132

    const int n0 = blockIdx.x * 64;

    #pragma unroll
    for (int it = 0; it < 8; it++) {
        int idx = tx + it * 256;
        int row = idx >> 5;
        int kq  = idx & 31;
        int n = n0 + row;
        float4 v = make_float4(0.f, 0.f, 0.f, 0.f);
        if (n < N_NODES) v = *(const float4*)&X[(size_t)n * INC + kq * 4];
        sXT[(kq * 4 + 0) * 72 + row] = v.x;
        sXT[(kq * 4 + 1) * 72 + row] = v.y;
        sXT[(kq * 4 + 2) * 72 + row] = v.z;
        sXT[(kq * 4 + 3) * 72 + row] = v.w;
    }

    const int c0 = (tx & 31) * 4;
    const int r0 = (tx >> 5) * 8;

    u64 ax0[8], ax1[8], av0[8], av1[8];
    #pragma unroll
    for (int i = 0; i < 8; i++) { ax0[i] = 0ull; ax1[i] = 0ull; av0[i] = 0ull; av1[i] = 0ull; }

    #pragma unroll
    for (int c = 0; c < 2; c++) {
        #pragma unroll
        for (int it = 0; it < 8; it++) {
            int idx = tx + it * 256;          // 64 rows * 32 float4
            int k  = idx >> 5;
            int cq = idx & 31;
            *(float4*)&sWx[k * 132 + cq * 4] = *(const float4*)&Wx[(c * 64 + k) * OUTC + cq * 4];
            *(float4*)&sWv[k * 132 + cq * 4] = *(const float4*)&Wv[(c * 64 + k) * OUTC + cq * 4];
        }
        __syncthreads();

        #pragma unroll 4
        for (int kk = 0; kk < 64; kk++) {
            int k = c * 64 + kk;
            ulonglong2 wx = *(ulonglong2*)&sWx[kk * 132 + c0];
            ulonglong2 wv = *(ulonglong2*)&sWv[kk * 132 + c0];
            float4 xa = *(float4*)&sXT[k * 72 + r0];
            float4 xb = *(float4*)&sXT[k * 72 + r0 + 4];
            float xs[8] = {xa.x, xa.y, xa.z, xa.w, xb.x, xb.y, xb.z, xb.w};
            #pragma unroll
            for (int i = 0; i < 8; i++) {
                u64 xx = pack2(xs[i]);
                fma2(ax0[i], xx, wx.x); fma2(ax1[i], xx, wx.y);
                fma2(av0[i], xx, wv.x); fma2(av1[i], xx, wv.y);
            }
        }
        __syncthreads();
    }

    float4 bx4 = *(const float4*)&bx[c0];
    float4 bv4 = *(const float4*)&bv[c0];
    float4 aa4 = *(const float4*)&a_vec[c0];
    const int lane = tx & 31;
    #pragma unroll
    for (int i = 0; i < 8; i++) {
        int n = n0 + r0 + i;
        if (n < N_NODES) {   // warp-uniform guard
            float2 x01 = unpack2(ax0[i]), x23 = unpack2(ax1[i]);
            float4 o = make_float4(x01.x + bx4.x, x01.y + bx4.y, x23.x + bx4.z, x23.y + bx4.w);
            *(float4*)&Xinit[(size_t)n * OUTC + c0] = o;
            float2 v01 = unpack2(av0[i]), v23 = unpack2(av1[i]);
            float4 f = make_float4(v01.x + bv4.x, v01.y + bv4.y, v23.x + bv4.z, v23.y + bv4.w);
            float part = f.x * aa4.x + f.y * aa4.y + f.z * aa4.z + f.w * aa4.w;
            #pragma unroll
            for (int off = 16; off; off >>= 1) part += __shfl_xor_sync(0xffffffffu, part, off);
            float s = part > 0.f ? part : 0.2f * part;
            float wv = expf(s);                         // warp-instruction cost, all lanes free
            uint2 pk; pk.x = f2h(wv * f.x, wv * f.y); pk.y = f2h(wv * f.z, wv * f.w);
            *(uint2*)&g_XW16[(size_t)n * 68 + lane * 2] = pk;     // P = w * X_feat
            if (lane == 0) g_XW16[(size_t)n * 68 + 64] = __float_as_uint(wv);
        }
    }
}

// ---------------- edge aggregation: 8 edges per warp (imbalance amortized) ----------------
// M16[e] = [ fp16(elu(sum P[v]/sum w_v)) | fp16(S[e]) ] — no multiplies in the loop (P premultiplied)
__global__ __launch_bounds__(256) void edge_agg_kernel(const float* __restrict__ S)
{
    const int warpId = blockIdx.x * 8 + (threadIdx.x >> 5);   // 3125*8 = 25000 warps
    const int lane = threadIdx.x & 31;
    const int e0 = warpId * 8;                                 // 8 consecutive edges per warp

    #pragma unroll 1
    for (int ew = 0; ew < 8; ew++) {
        const int e = e0 + ew;
        const int base = __ldg(&g_baseE[e]);
        const int deg  = __ldg(&g_zero[e]);
        float2 accA = make_float2(0.f, 0.f);
        float2 accB = make_float2(0.f, 0.f);
        float denom = 0.f;
        for (int j = 0; j < deg; j++) {
            int v = __ldg(&g_csrE_v[base + j]);              // warp-broadcast
            const uint32_t* r = &g_XW16[(size_t)v * 68];     // one base: payload [lane*2], w [+64]
            uint2 p = *(const uint2*)&r[lane * 2];
            denom += __uint_as_float(__ldg(&r[64]));
            float2 f0 = h2f(p.x), f1 = h2f(p.y);
            accA.x += f0.x; accA.y += f0.y;
            accB.x += f1.x; accB.y += f1.y;
        }
        float inv = (deg > 0) ? (1.f / denom) : 0.f;
        uint2 pk;
        pk.x = f2h(elu1(accA.x * inv), elu1(accA.y * inv));
        pk.y = f2h(elu1(accB.x * inv), elu1(accB.y * inv));
        *(uint2*)&g_M16[(size_t)e * 96 + lane * 2] = pk;
        // append fp16(S[e]) — read once per edge instead of once per nnz in the node pass
        float2 s2 = *(const float2*)&S[(size_t)e * STAR_ + lane * 2];
        g_M16[(size_t)e * 96 + 64 + lane] = f2h(s2.x, s2.y);
    }
}

// ---------------- fused node aggregation + GEMM: out = X_init + (deg>0 ? elu(mean@Wt + bt) : 0) ----------------
#define SMROW 200
__global__ __launch_bounds__(256, 3) void node_gemm_fused_kernel(
    const float* __restrict__ Wt, const float* __restrict__ bt, float* __restrict__ out)
{
    extern __shared__ float sm[];
    float* sM = sm;                        // 64*200
    float* sW = sm + 64 * SMROW;           // 32*132
    int*  sDeg = (int*)(sW + 32 * 132);    // 64

    const int tx = threadIdx.x;
    const int wid = tx >> 5, lane = tx & 31;
    const int n0 = blockIdx.x * 64;

    // ---- phase 1: gather means, pairwise-fp16 reduction (HADD2 pairs, fp32 accumulate) ----
    #pragma unroll 1
    for (int m = 0; m < 8; m++) {
        int row = wid * 8 + m;
        int n = n0 + row;
        float2 accA = make_float2(0.f, 0.f);
        float2 accB = make_float2(0.f, 0.f);
        float2 accS = make_float2(0.f, 0.f);
        int deg = 0;
        if (n < N_NODES) {
            int base = g_baseV[n];
            deg = g_zero[N_EDGES + n];
            int j = 0;
            for (; j + 1 < deg; j += 2) {
                int e0 = __ldg(&g_csrV_e[base + j]);
                int e1 = __ldg(&g_csrV_e[base + j + 1]);
                const uint32_t* r0 = &g_M16[(size_t)e0 * 96];
                const uint32_t* r1 = &g_M16[(size_t)e1 * 96];
                uint32_t a0 = __ldg(&r0[lane]),      b0 = __ldg(&r1[lane]);
                uint32_t a1 = __ldg(&r0[32 + lane]), b1 = __ldg(&r1[32 + lane]);
                uint32_t a2 = __ldg(&r0[64 + lane]), b2 = __ldg(&r1[64 + lane]);
                float2 pA = h2f(hadd2u(a0, b0));
                float2 pB = h2f(hadd2u(a1, b1));
                float2 pS = h2f(hadd2u(a2, b2));
                accA.x += pA.x; accA.y += pA.y;
                accB.x += pB.x; accB.y += pB.y;
                accS.x += pS.x; accS.y += pS.y;
            }
            if (j < deg) {   // odd tail in fp32
                int e0 = __ldg(&g_csrV_e[base + j]);
                const uint32_t* r0 = &g_M16[(size_t)e0 * 96];
                float2 f0 = h2f(__ldg(&r0[lane]));
                float2 f1 = h2f(__ldg(&r0[32 + lane]));
                float2 f2 = h2f(__ldg(&r0[64 + lane]));
                accA.x += f0.x; accA.y += f0.y;
                accB.x += f1.x; accB.y += f1.y;
                accS.x += f2.x; accS.y += f2.y;
            }
        }
        float inv = 1.f / fmaxf((float)deg, 1.f);
        accA.x *= inv; accA.y *= inv;
        accB.x *= inv; accB.y *= inv;
        accS.x *= inv; accS.y *= inv;
        *(float2*)&sM[row * SMROW + 2 * lane] = accA;
        *(float2*)&sM[row * SMROW + 64 + 2 * lane] = accB;
        *(float2*)&sM[row * SMROW + 128 + 2 * lane] = accS;
        if (lane == 0) sDeg[row] = deg;
    }
    __syncthreads();

    // ---- phase 2: GEMM (64x128, K=192, Wt in 6 chunks of 32 rows) ----
    const int c0 = (tx & 31) * 4;
    const int r0 = (tx >> 5) * 8;

    u64 a0[8], a1[8];
    #pragma unroll
    for (int i = 0; i < 8; i++) { a0[i] = 0ull; a1[i] = 0ull; }

    #pragma unroll 1
    for (int c = 0; c < 6; c++) {
        #pragma unroll
        for (int it = 0; it < 4; it++) {
            int idx = tx + it * 256;      // 32 rows * 32 float4
            int k  = idx >> 5;
            int cq = idx & 31;
            *(float4*)&sW[k * 132 + cq * 4] = *(const float4*)&Wt[(c * 32 + k) * OUTC + cq * 4];
        }
        __syncthreads();

        #pragma unroll 4
        for (int kk = 0; kk < 32; kk++) {
            int k = c * 32 + kk;
            ulonglong2 w2 = *(ulonglong2*)&sW[kk * 132 + c0];
            #pragma unroll
            for (int i = 0; i < 8; i++) {
                u64 xx = pack2(sM[(r0 + i) * SMROW + k]);   // warp-broadcast LDS
                fma2(a0[i], xx, w2.x); fma2(a1[i], xx, w2.y);
            }
        }
        __syncthreads();
    }

    float4 bt4 = *(const float4*)&bt[c0];
    #pragma unroll
    for (int i = 0; i < 8; i++) {
        int n = n0 + r0 + i;
        if (n < N_NODES) {
            size_t oidx = (size_t)n * OUTC + c0;
            float4 o = *(const float4*)&out[oidx];           // X_init
            if (sDeg[r0 + i] > 0) {                          // isolated node -> elu(0)=0
                float2 p01 = unpack2(a0[i]), p23 = unpack2(a1[i]);
                o.x += elu1(p01.x + bt4.x);
                o.y += elu1(p01.y + bt4.y);
                o.z += elu1(p23.x + bt4.z);
                o.w += elu1(p23.y + bt4.w);
            }
            *(float4*)&out[oidx] = o;
        }
    }
}

// ---------------- launch ----------------
extern "C" void kernel_launch(void* const* d_in, const int* in_sizes, int n_in,
                              void* d_out, int out_size)
{
    const float* X  = (const float*)d_in[0];
    const int*   V  = (const int*)d_in[1];
    const int*   E  = (const int*)d_in[2];
    const float* S  = (const float*)d_in[3];
    const float* Wx = (const float*)d_in[4];
    const float* bx = (const float*)d_in[5];
    const float* Wv = (const float*)d_in[6];
    const float* bv = (const float*)d_in[7];
    const float* a  = (const float*)d_in[8];
    const float* Wt = (const float*)d_in[9];
    const float* bt = (const float*)d_in[10];
    float* out = (float*)d_out;

    void* p_zero;
    cudaGetSymbolAddress(&p_zero, g_zero);
    cudaMemsetAsync(p_zero, 0, (size_t)(N_EDGES + N_NODES + 2) * sizeof(int));

    const int smem1 = (128 * 72 + 2 * 64 * 132) * (int)sizeof(float);           // 104448
    const int smem2 = (64 * SMROW + 32 * 132) * (int)sizeof(float) + 64 * 4;    // 68352
    cudaFuncSetAttribute(gemm_scatter_kernel,    cudaFuncAttributeMaxDynamicSharedMemorySize, smem1);
    cudaFuncSetAttribute(node_gemm_fused_kernel, cudaFuncAttributeMaxDynamicSharedMemorySize, smem2);

    hist_kernel<<<6250, 256>>>(V, E);
    alloc_kernel<<<1173, 256>>>();
    gemm_scatter_kernel<<<GX_BLOCKS + SC_BLOCKS, 256, smem1>>>(X, Wx, bx, Wv, bv, a, V, E, out);
    edge_agg_kernel<<<3125, 256>>>(S);
    node_gemm_fused_kernel<<<1563, 256, smem2>>>(Wt, bt, out);
}

// round 17
// speedup vs baseline: 1.0422x; 1.0244x over previous
#include <cuda_runtime.h>
#include <cuda_fp16.h>
#include <math.h>
#include <stdint.h>

#define N_NODES 100000
#define N_EDGES 200000
#define NNZ_    1600000
#define INC 128
#define OUTC 128
#define STAR_ 64
#define KTOT 192

#define GX_BLOCKS 1563
#define SC_BLOCKS 6250

typedef unsigned long long u64;

// ---------------- device scratch (allocation-free) ----------------
// packed per-node row: [P = w*X_feat fp16 (64 uint32) | w fp32-bits (1) | pad (3)]  stride 68
__device__ uint32_t g_XW16[(size_t)N_NODES * 68];      // 27.2 MB
// combined fp16 message row per edge: [Yv2e (128 halves) | S (64 halves)] = 96 uint32
__device__ uint32_t g_M16[(size_t)N_EDGES * 96];       // 76.8 MB

// zero region: [histE | histV | alloc_ctr(2)]  -> single memset
__device__ int g_zero[N_EDGES + N_NODES + 2];
__device__ int g_baseE[N_EDGES];
__device__ int g_baseV[N_NODES];
__device__ int g_rankE[NNZ_];
__device__ int g_rankV[NNZ_];
__device__ int g_csrE_v[NNZ_];
__device__ int g_csrV_e[NNZ_];

// ---------------- helpers ----------------
__device__ __forceinline__ float elu1(float x) {
    return x > 0.f ? x : expm1f(x);
}
// packed f32x2 FMA (Blackwell FFMA2 path via PTX)
__device__ __forceinline__ u64 pack2(float v) {
    u64 r; asm("mov.b64 %0, {%1, %1};" : "=l"(r) : "f"(v)); return r;
}
__device__ __forceinline__ void fma2(u64& d, u64 a, u64 b) {
    asm("fma.rn.f32x2 %0, %1, %2, %0;" : "+l"(d) : "l"(a), "l"(b));
}
__device__ __forceinline__ float2 unpack2(u64 v) {
    float2 r; asm("mov.b64 {%0, %1}, %2;" : "=f"(r.x), "=f"(r.y) : "l"(v)); return r;
}
__device__ __forceinline__ float2 h2f(uint32_t u) {
    return __half22float2(*reinterpret_cast<__half2*>(&u));
}
__device__ __forceinline__ uint32_t f2h(float a, float b) {
    __half2 h = __floats2half2_rn(a, b);
    return *reinterpret_cast<uint32_t*>(&h);
}
__device__ __forceinline__ uint32_t hadd2u(uint32_t a, uint32_t b) {
    __half2 r = __hadd2(*reinterpret_cast<const __half2*>(&a), *reinterpret_cast<const __half2*>(&b));
    return *reinterpret_cast<uint32_t*>(&r);
}

// ---------------- histogram + rank capture ----------------
__global__ __launch_bounds__(256) void hist_kernel(const int* __restrict__ V, const int* __restrict__ E)
{
    int i = blockIdx.x * 256 + threadIdx.x;     // 6250*256 = NNZ exact
    int e = __ldg(&E[i]);
    int v = __ldg(&V[i]);
    g_rankE[i] = atomicAdd(&g_zero[e], 1);
    g_rankV[i] = atomicAdd(&g_zero[N_EDGES + v], 1);
}

// ---------------- segment-base allocation: edges (blocks 0..781) + nodes (blocks 782..1172) ----------------
__global__ __launch_bounds__(256) void alloc_kernel()
{
    __shared__ int s_warp[8];
    __shared__ int s_base;
    const int t = threadIdx.x;
    const bool isE = blockIdx.x < 782;
    const int i = (isE ? blockIdx.x : (blockIdx.x - 782)) * 256 + t;
    const int len = isE ? N_EDGES : N_NODES;
    const int* hist = isE ? g_zero : (g_zero + N_EDGES);
    int* base = isE ? g_baseE : g_baseV;
    int* ctr  = &g_zero[N_EDGES + N_NODES + (isE ? 0 : 1)];

    const int lane = t & 31, wid = t >> 5;
    int v = (i < len) ? hist[i] : 0;
    int x = v;
    #pragma unroll
    for (int off = 1; off < 32; off <<= 1) {
        int y = __shfl_up_sync(0xffffffffu, x, off);
        if (lane >= off) x += y;
    }
    if (lane == 31) s_warp[wid] = x;
    __syncthreads();
    if (wid == 0) {
        int orig = (lane < 8) ? s_warp[lane] : 0;
        int s = orig;
        #pragma unroll
        for (int off = 1; off < 8; off <<= 1) {
            int y = __shfl_up_sync(0xffffffffu, s, off);
            if (lane >= off) s += y;
        }
        if (lane == 7) s_base = atomicAdd(ctr, s);
        if (lane < 8) s_warp[lane] = s - orig;
    }
    __syncthreads();
    if (i < len) base[i] = (x - v) + s_warp[wid] + s_base;
}

// ---------------- fused: gemm_x (blocks 0..1562) || atomic-free scatter (blocks 1563..7812) ----------------
__global__ __launch_bounds__(256, 2) void gemm_scatter_kernel(
    const float* __restrict__ X, const float* __restrict__ Wx, const float* __restrict__ bx,
    const float* __restrict__ Wv, const float* __restrict__ bv, const float* __restrict__ a_vec,
    const int* __restrict__ V, const int* __restrict__ E,
    float* __restrict__ Xinit)
{
    const int tx = threadIdx.x;

    if (blockIdx.x >= GX_BLOCKS) {
        // ----- scatter branch: pure writes, no atomics -----
        int i = (blockIdx.x - GX_BLOCKS) * 256 + tx;     // NNZ exact
        int v = __ldg(&V[i]);
        int e = __ldg(&E[i]);
        g_csrE_v[__ldg(&g_baseE[e]) + g_rankE[i]] = v;
        g_csrV_e[__ldg(&g_baseV[v]) + g_rankV[i]] = e;
        return;
    }

    // ----- gemm_x branch -----
    extern __shared__ float sm[];
    float* sXT = sm;                 // 128*72  (k-major, transposed X tile)
    float* sWx = sm + 128 * 72;      // 64*132  (one k-chunk)
    float* sWv = sWx + 64 * 132;     // 64*132

    const int n0 = blockIdx.x * 64;

    #pragma unroll
    for (int it = 0; it < 8; it++) {
        int idx = tx + it * 256;
        int row = idx >> 5;
        int kq  = idx & 31;
        int n = n0 + row;
        float4 v = make_float4(0.f, 0.f, 0.f, 0.f);
        if (n < N_NODES) v = *(const float4*)&X[(size_t)n * INC + kq * 4];
        sXT[(kq * 4 + 0) * 72 + row] = v.x;
        sXT[(kq * 4 + 1) * 72 + row] = v.y;
        sXT[(kq * 4 + 2) * 72 + row] = v.z;
        sXT[(kq * 4 + 3) * 72 + row] = v.w;
    }

    const int c0 = (tx & 31) * 4;
    const int r0 = (tx >> 5) * 8;

    u64 ax0[8], ax1[8], av0[8], av1[8];
    #pragma unroll
    for (int i = 0; i < 8; i++) { ax0[i] = 0ull; ax1[i] = 0ull; av0[i] = 0ull; av1[i] = 0ull; }

    #pragma unroll
    for (int c = 0; c < 2; c++) {
        #pragma unroll
        for (int it = 0; it < 8; it++) {
            int idx = tx + it * 256;          // 64 rows * 32 float4
            int k  = idx >> 5;
            int cq = idx & 31;
            *(float4*)&sWx[k * 132 + cq * 4] = *(const float4*)&Wx[(c * 64 + k) * OUTC + cq * 4];
            *(float4*)&sWv[k * 132 + cq * 4] = *(const float4*)&Wv[(c * 64 + k) * OUTC + cq * 4];
        }
        __syncthreads();

        #pragma unroll 4
        for (int kk = 0; kk < 64; kk++) {
            int k = c * 64 + kk;
            ulonglong2 wx = *(ulonglong2*)&sWx[kk * 132 + c0];
            ulonglong2 wv = *(ulonglong2*)&sWv[kk * 132 + c0];
            float4 xa = *(float4*)&sXT[k * 72 + r0];
            float4 xb = *(float4*)&sXT[k * 72 + r0 + 4];
            float xs[8] = {xa.x, xa.y, xa.z, xa.w, xb.x, xb.y, xb.z, xb.w};
            #pragma unroll
            for (int i = 0; i < 8; i++) {
                u64 xx = pack2(xs[i]);
                fma2(ax0[i], xx, wx.x); fma2(ax1[i], xx, wx.y);
                fma2(av0[i], xx, wv.x); fma2(av1[i], xx, wv.y);
            }
        }
        __syncthreads();
    }

    float4 bx4 = *(const float4*)&bx[c0];
    float4 bv4 = *(const float4*)&bv[c0];
    float4 aa4 = *(const float4*)&a_vec[c0];
    const int lane = tx & 31;
    #pragma unroll
    for (int i = 0; i < 8; i++) {
        int n = n0 + r0 + i;
        if (n < N_NODES) {   // warp-uniform guard
            float2 x01 = unpack2(ax0[i]), x23 = unpack2(ax1[i]);
            float4 o = make_float4(x01.x + bx4.x, x01.y + bx4.y, x23.x + bx4.z, x23.y + bx4.w);
            *(float4*)&Xinit[(size_t)n * OUTC + c0] = o;
            float2 v01 = unpack2(av0[i]), v23 = unpack2(av1[i]);
            float4 f = make_float4(v01.x + bv4.x, v01.y + bv4.y, v23.x + bv4.z, v23.y + bv4.w);
            float part = f.x * aa4.x + f.y * aa4.y + f.z * aa4.z + f.w * aa4.w;
            #pragma unroll
            for (int off = 16; off; off >>= 1) part += __shfl_xor_sync(0xffffffffu, part, off);
            float s = part > 0.f ? part : 0.2f * part;
            float wv = expf(s);                         // warp-instruction cost, all lanes free
            uint2 pk; pk.x = f2h(wv * f.x, wv * f.y); pk.y = f2h(wv * f.z, wv * f.w);
            *(uint2*)&g_XW16[(size_t)n * 68 + lane * 2] = pk;     // P = w * X_feat
            if (lane == 0) g_XW16[(size_t)n * 68 + 64] = __float_as_uint(wv);
        }
    }
}

// ---------------- edge aggregation: 8 edges per warp, fp16-native accumulation ----------------
// M16[e] = [ fp16(elu(sum P[v]/sum w_v)) | fp16(S[e]) ] — HADD2 accumulators, fp32 only for denom+epilogue
__global__ __launch_bounds__(256) void edge_agg_kernel(const float* __restrict__ S)
{
    const int warpId = blockIdx.x * 8 + (threadIdx.x >> 5);   // 3125*8 = 25000 warps
    const int lane = threadIdx.x & 31;
    const int e0 = warpId * 8;                                 // 8 consecutive edges per warp

    #pragma unroll 1
    for (int ew = 0; ew < 8; ew++) {
        const int e = e0 + ew;
        const int base = __ldg(&g_baseE[e]);
        const int deg  = __ldg(&g_zero[e]);
        uint32_t accA = 0u, accB = 0u;                         // half2 {+0,+0}
        float denom = 0.f;
        for (int j = 0; j < deg; j++) {
            int v = __ldg(&g_csrE_v[base + j]);                // warp-broadcast
            const uint32_t* r = &g_XW16[(size_t)v * 68];       // one base: payload [lane*2], w [+64]
            uint2 p = *(const uint2*)&r[lane * 2];
            denom += __uint_as_float(__ldg(&r[64]));
            accA = hadd2u(accA, p.x);
            accB = hadd2u(accB, p.y);
        }
        float inv = (deg > 0) ? (1.f / denom) : 0.f;
        float2 fA = h2f(accA), fB = h2f(accB);
        uint2 pk;
        pk.x = f2h(elu1(fA.x * inv), elu1(fA.y * inv));
        pk.y = f2h(elu1(fB.x * inv), elu1(fB.y * inv));
        *(uint2*)&g_M16[(size_t)e * 96 + lane * 2] = pk;
        // append fp16(S[e]) — read once per edge instead of once per nnz in the node pass
        float2 s2 = *(const float2*)&S[(size_t)e * STAR_ + lane * 2];
        g_M16[(size_t)e * 96 + 64 + lane] = f2h(s2.x, s2.y);
    }
}

// ---------------- fused node aggregation + GEMM: out = X_init + (deg>0 ? elu(mean@Wt + bt) : 0) ----------------
#define SMROW 200
__global__ __launch_bounds__(256, 3) void node_gemm_fused_kernel(
    const float* __restrict__ Wt, const float* __restrict__ bt, float* __restrict__ out)
{
    extern __shared__ float sm[];
    float* sM = sm;                        // 64*200
    float* sW = sm + 64 * SMROW;           // 32*132
    int*  sDeg = (int*)(sW + 32 * 132);    // 64

    const int tx = threadIdx.x;
    const int wid = tx >> 5, lane = tx & 31;
    const int n0 = blockIdx.x * 64;

    // ---- phase 1: gather means, pairwise-fp16 reduction (HADD2 pairs, fp32 accumulate) ----
    #pragma unroll 1
    for (int m = 0; m < 8; m++) {
        int row = wid * 8 + m;
        int n = n0 + row;
        float2 accA = make_float2(0.f, 0.f);
        float2 accB = make_float2(0.f, 0.f);
        float2 accS = make_float2(0.f, 0.f);
        int deg = 0;
        if (n < N_NODES) {
            int base = g_baseV[n];
            deg = g_zero[N_EDGES + n];
            int j = 0;
            for (; j + 1 < deg; j += 2) {
                int e0 = __ldg(&g_csrV_e[base + j]);
                int e1 = __ldg(&g_csrV_e[base + j + 1]);
                const uint32_t* r0 = &g_M16[(size_t)e0 * 96];
                const uint32_t* r1 = &g_M16[(size_t)e1 * 96];
                uint32_t a0 = __ldg(&r0[lane]),      b0 = __ldg(&r1[lane]);
                uint32_t a1 = __ldg(&r0[32 + lane]), b1 = __ldg(&r1[32 + lane]);
                uint32_t a2 = __ldg(&r0[64 + lane]), b2 = __ldg(&r1[64 + lane]);
                float2 pA = h2f(hadd2u(a0, b0));
                float2 pB = h2f(hadd2u(a1, b1));
                float2 pS = h2f(hadd2u(a2, b2));
                accA.x += pA.x; accA.y += pA.y;
                accB.x += pB.x; accB.y += pB.y;
                accS.x += pS.x; accS.y += pS.y;
            }
            if (j < deg) {   // odd tail in fp32
                int e0 = __ldg(&g_csrV_e[base + j]);
                const uint32_t* r0 = &g_M16[(size_t)e0 * 96];
                float2 f0 = h2f(__ldg(&r0[lane]));
                float2 f1 = h2f(__ldg(&r0[32 + lane]));
                float2 f2 = h2f(__ldg(&r0[64 + lane]));
                accA.x += f0.x; accA.y += f0.y;
                accB.x += f1.x; accB.y += f1.y;
                accS.x += f2.x; accS.y += f2.y;
            }
        }
        float inv = 1.f / fmaxf((float)deg, 1.f);
        accA.x *= inv; accA.y *= inv;
        accB.x *= inv; accB.y *= inv;
        accS.x *= inv; accS.y *= inv;
        *(float2*)&sM[row * SMROW + 2 * lane] = accA;
        *(float2*)&sM[row * SMROW + 64 + 2 * lane] = accB;
        *(float2*)&sM[row * SMROW + 128 + 2 * lane] = accS;
        if (lane == 0) sDeg[row] = deg;
    }
    __syncthreads();

    // ---- phase 2: GEMM (64x128, K=192, Wt in 6 chunks of 32 rows) ----
    const int c0 = (tx & 31) * 4;
    const int r0 = (tx >> 5) * 8;

    u64 a0[8], a1[8];
    #pragma unroll
    for (int i = 0; i < 8; i++) { a0[i] = 0ull; a1[i] = 0ull; }

    #pragma unroll 1
    for (int c = 0; c < 6; c++) {
        #pragma unroll
        for (int it = 0; it < 4; it++) {
            int idx = tx + it * 256;      // 32 rows * 32 float4
            int k  = idx >> 5;
            int cq = idx & 31;
            *(float4*)&sW[k * 132 + cq * 4] = *(const float4*)&Wt[(c * 32 + k) * OUTC + cq * 4];
        }
        __syncthreads();

        #pragma unroll 4
        for (int kk = 0; kk < 32; kk++) {
            int k = c * 32 + kk;
            ulonglong2 w2 = *(ulonglong2*)&sW[kk * 132 + c0];
            #pragma unroll
            for (int i = 0; i < 8; i++) {
                u64 xx = pack2(sM[(r0 + i) * SMROW + k]);   // warp-broadcast LDS
                fma2(a0[i], xx, w2.x); fma2(a1[i], xx, w2.y);
            }
        }
        __syncthreads();
    }

    float4 bt4 = *(const float4*)&bt[c0];
    #pragma unroll
    for (int i = 0; i < 8; i++) {
        int n = n0 + r0 + i;
        if (n < N_NODES) {
            size_t oidx = (size_t)n * OUTC + c0;
            float4 o = *(const float4*)&out[oidx];           // X_init
            if (sDeg[r0 + i] > 0) {                          // isolated node -> elu(0)=0
                float2 p01 = unpack2(a0[i]), p23 = unpack2(a1[i]);
                o.x += elu1(p01.x + bt4.x);
                o.y += elu1(p01.y + bt4.y);
                o.z += elu1(p23.x + bt4.z);
                o.w += elu1(p23.y + bt4.w);
            }
            *(float4*)&out[oidx] = o;
        }
    }
}

// ---------------- launch ----------------
extern "C" void kernel_launch(void* const* d_in, const int* in_sizes, int n_in,
                              void* d_out, int out_size)
{
    const float* X  = (const float*)d_in[0];
    const int*   V  = (const int*)d_in[1];
    const int*   E  = (const int*)d_in[2];
    const float* S  = (const float*)d_in[3];
    const float* Wx = (const float*)d_in[4];
    const float* bx = (const float*)d_in[5];
    const float* Wv = (const float*)d_in[6];
    const float* bv = (const float*)d_in[7];
    const float* a  = (const float*)d_in[8];
    const float* Wt = (const float*)d_in[9];
    const float* bt = (const float*)d_in[10];
    float* out = (float*)d_out;

    void* p_zero;
    cudaGetSymbolAddress(&p_zero, g_zero);
    cudaMemsetAsync(p_zero, 0, (size_t)(N_EDGES + N_NODES + 2) * sizeof(int));

    const int smem1 = (128 * 72 + 2 * 64 * 132) * (int)sizeof(float);           // 104448
    const int smem2 = (64 * SMROW + 32 * 132) * (int)sizeof(float) + 64 * 4;    // 68352
    cudaFuncSetAttribute(gemm_scatter_kernel,    cudaFuncAttributeMaxDynamicSharedMemorySize, smem1);
    cudaFuncSetAttribute(node_gemm_fused_kernel, cudaFuncAttributeMaxDynamicSharedMemorySize, smem2);

    hist_kernel<<<6250, 256>>>(V, E);
    alloc_kernel<<<1173, 256>>>();
    gemm_scatter_kernel<<<GX_BLOCKS + SC_BLOCKS, 256, smem1>>>(X, Wx, bx, Wv, bv, a, V, E, out);
    edge_agg_kernel<<<3125, 256>>>(S);
    node_gemm_fused_kernel<<<1563, 256, smem2>>>(Wt, bt, out);
}